// round 16
// baseline (speedup 1.0000x reference)
#include <cuda_runtime.h>
#include <cuda_bf16.h>
#include <mma.h>
#include <math.h>
#include <cstdint>

using namespace nvcuda;

// Problem constants (fixed by the dataset)
#define NN 131072        // nodes
#define NE 2097152       // edges

// ---------------------------------------------------------------------------
// Scratch (allocation-free rule: __device__ globals)
// ---------------------------------------------------------------------------
__device__ __align__(16) float g_h1[NN * 32];   // after block3
__device__ __align__(16) float g_h2[NN * 64];   // after block2
__device__ __align__(16) float g_rdeg[NN];      // 1/max(deg,1)

__device__ __align__(16) float g_W1t[128 * 128];  // combined [Ws1;Wn1], tf32
__device__ __align__(16) float g_W2t[64 * 64];    // combined [Ws2;Wn2], tf32
__device__ __align__(16) float g_W3f[32 * 32];    // folded [Wl@Ws3; Wl@Wn3], fp32
__device__ __align__(16) float g_c0[32];          // bl@Ws3 + b3
__device__ __align__(16) float g_c1[32];          // bl@Wn3

__device__ int g_deg[NN];
__device__ int g_rowoff[NN];
__device__ int g_cursor[NN];
__device__ int g_col[NE];
__device__ int g_bsum[512];

// ---------------------------------------------------------------------------
// CSR construction
// ---------------------------------------------------------------------------
__global__ void zero2_int(int* __restrict__ a, int* __restrict__ b) {
    int i = blockIdx.x * blockDim.x + threadIdx.x;
    if (i < NN) { a[i] = 0; b[i] = 0; }
}

__global__ void deg_kernel(const int* __restrict__ dst, int* __restrict__ deg) {
    int e = blockIdx.x * blockDim.x + threadIdx.x;
    if (e < NE) atomicAdd(&deg[dst[e]], 1);
}

// Per-block exclusive scan of 256 elems + block totals + fused rdeg.
__global__ void scanA(const int* __restrict__ deg, int* __restrict__ part,
                      int* __restrict__ bsum, float* __restrict__ rdeg) {
    __shared__ int s[256];
    int t = threadIdx.x;
    int i = blockIdx.x * 256 + t;
    int v = deg[i];
    rdeg[i] = 1.0f / fmaxf((float)v, 1.0f);
    s[t] = v;
    __syncthreads();
    for (int o = 1; o < 256; o <<= 1) {
        int u = (t >= o) ? s[t - o] : 0;
        __syncthreads();
        s[t] += u;
        __syncthreads();
    }
    part[i] = s[t] - v;
    if (t == 255) bsum[blockIdx.x] = s[255];
}

__global__ void scanB(int* __restrict__ bsum) {
    __shared__ int s[512];
    int t = threadIdx.x;
    int v = bsum[t];
    s[t] = v;
    __syncthreads();
    for (int o = 1; o < 512; o <<= 1) {
        int u = (t >= o) ? s[t - o] : 0;
        __syncthreads();
        s[t] += u;
        __syncthreads();
    }
    bsum[t] = s[t] - v;
}

__global__ void scanC(int* __restrict__ part, const int* __restrict__ bsum) {
    int i = blockIdx.x * 256 + threadIdx.x;
    part[i] += bsum[blockIdx.x];
}

__global__ void fill_kernel(const int* __restrict__ src, const int* __restrict__ dst,
                            const int* __restrict__ rowoff, int* __restrict__ cursor,
                            int* __restrict__ col) {
    int e = blockIdx.x * blockDim.x + threadIdx.x;
    if (e >= NE) return;
    int d = dst[e];
    int pos = rowoff[d] + atomicAdd(&cursor[d], 1);
    col[pos] = src[e];
}

// ---------------------------------------------------------------------------
// Weight prep (once per launch):
//  blocks 0..63: combined big-layer weights -> tf32 globals
//  block 64:     fold Linear(16,16) into block3 (aggregation/affine commute):
//                W3f = [Wl@Ws3 ; Wl@Wn3], c0 = bl@Ws3 + b3, c1 = bl@Wn3
// ---------------------------------------------------------------------------
__device__ __forceinline__ float f2tf32(float x) {
    float y;
    asm("cvt.rna.tf32.f32 %0, %1;" : "=f"(y) : "f"(x));
    return y;
}

__global__ void prep_w(const float* __restrict__ Ws1, const float* __restrict__ Wn1,
                       const float* __restrict__ Ws2, const float* __restrict__ Wn2,
                       const float* __restrict__ Wl,  const float* __restrict__ bl,
                       const float* __restrict__ Ws3, const float* __restrict__ Wn3,
                       const float* __restrict__ b3) {
    if (blockIdx.x < 64) {
        int i = blockIdx.x * 256 + threadIdx.x;
        if (i < 128 * 128) {
            int k = i >> 7, c = i & 127;
            float w = (k < 64) ? Ws1[k * 128 + c] : Wn1[(k - 64) * 128 + c];
            g_W1t[i] = f2tf32(w);
        }
        if (i < 64 * 64) {
            int k = i >> 6, c = i & 63;
            float w = (k < 32) ? Ws2[k * 64 + c] : Wn2[(k - 32) * 64 + c];
            g_W2t[i] = f2tf32(w);
        }
    } else {
        // Fold block
        for (int i = threadIdx.x; i < 32 * 32; i += 256) {
            int k = i >> 5, c = i & 31;
            float s = 0.f;
            if (k < 16) {
                for (int j = 0; j < 16; j++) s += Wl[k * 16 + j] * Ws3[j * 32 + c];
            } else {
                for (int j = 0; j < 16; j++) s += Wl[(k - 16) * 16 + j] * Wn3[j * 32 + c];
            }
            g_W3f[i] = s;
        }
        if (threadIdx.x < 32) {
            int c = threadIdx.x;
            float s0 = 0.f, s1 = 0.f;
            for (int j = 0; j < 16; j++) {
                s0 += bl[j] * Ws3[j * 32 + c];
                s1 += bl[j] * Wn3[j * 32 + c];
            }
            g_c0[c] = s0 + b3[c];
            g_c1[c] = s1;
        }
    }
}

// ---------------------------------------------------------------------------
// Activations
// ---------------------------------------------------------------------------
template <int ACT>
__device__ __forceinline__ float actf(float x) {
    if (ACT == 1) return fmaxf(x, 0.f);
    if (ACT == 2) return 1.0f / (1.0f + __expf(-x));
    return x;
}

__device__ __forceinline__ void f4add(float4& a, const float4& v) {
    a.x += v.x; a.y += v.y; a.z += v.z; a.w += v.w;
}

// ---------------------------------------------------------------------------
// Fused block3: h1 = relu( x@Wsx + agg(x)@Wnx + c0 + [deg>0]*c1 )
// (Linear(16,16) folded in; aggregation commutes with the affine map.)
// 256 threads, BN=64 nodes. Gather unrolled 2x with independent accumulators.
// LDI = K+4 = 36 floats/row -> 144-byte row stride, 16B-aligned for float4.
// ---------------------------------------------------------------------------
__global__ void __launch_bounds__(256)
block3_fused_kernel(const float* __restrict__ x,
                    const int* __restrict__ rowoff,
                    const int* __restrict__ deg,
                    const int* __restrict__ col,
                    const float* __restrict__ rdeg,
                    const float* __restrict__ W3f,
                    const float* __restrict__ c0,
                    const float* __restrict__ c1,
                    float* __restrict__ out) {
    constexpr int CIN = 16, COUT = 32, K = 32, BN = 64;
    constexpr int LDI = K + 4;           // 36 floats = 144B rows (16B aligned)
    constexpr int C4 = CIN / 4;          // 4
    constexpr int SLOTS = 32 / C4;       // 8
    constexpr int TX = COUT / 4;         // 8
    constexpr int TY = 256 / TX;         // 32
    constexpr int NT = BN / TY;          // 2

    __shared__ float Ws[K * COUT];
    __shared__ float C0[COUT], C1[COUT];
    __shared__ __align__(16) float Is[BN * LDI];
    __shared__ float sflag[BN];

    const int tid  = threadIdx.x;
    const int base = blockIdx.x * BN;

    for (int i = tid; i < K * COUT; i += 256) Ws[i] = W3f[i];
    if (tid < COUT) { C0[tid] = c0[tid]; C1[tid] = c1[tid]; }

    // Phase 1a: stage x rows
    for (int i = tid; i < BN * C4; i += 256) {
        int n = i / C4, q = i % C4;
        float4 v = reinterpret_cast<const float4*>(x)[(size_t)(base + n) * C4 + q];
        *reinterpret_cast<float4*>(&Is[n * LDI + q * 4]) = v;
    }

    // Phase 1b: in-block gather of x -> Is[n][16..32), 8 nodes per warp
    {
        const int warp = tid >> 5;
        const int lane = tid & 31;
        const int slot = lane / C4;
        const int c    = lane % C4;
        const float4* x4 = reinterpret_cast<const float4*>(x);

#pragma unroll
        for (int j = 0; j < BN / 8; j++) {
            int nloc = warp * (BN / 8) + j;
            int node = base + nloc;
            int st = rowoff[node];
            int d  = deg[node];
            float4 a0 = make_float4(0, 0, 0, 0), a1 = make_float4(0, 0, 0, 0);
            int ni = slot;
            for (; ni + SLOTS < d; ni += 2 * SLOTS) {
                int i0 = col[st + ni];
                int i1 = col[st + ni + SLOTS];
                float4 v0 = x4[(size_t)i0 * C4 + c];
                float4 v1 = x4[(size_t)i1 * C4 + c];
                f4add(a0, v0);
                f4add(a1, v1);
            }
            if (ni < d) {
                int i0 = col[st + ni];
                f4add(a0, x4[(size_t)i0 * C4 + c]);
            }
            f4add(a0, a1);
#pragma unroll
            for (int off = 16; off >= C4; off >>= 1) {
                a0.x += __shfl_xor_sync(0xFFFFFFFFu, a0.x, off);
                a0.y += __shfl_xor_sync(0xFFFFFFFFu, a0.y, off);
                a0.z += __shfl_xor_sync(0xFFFFFFFFu, a0.z, off);
                a0.w += __shfl_xor_sync(0xFFFFFFFFu, a0.w, off);
            }
            if (lane < C4) {
                float r = rdeg[node];
                float* dptr = &Is[nloc * LDI + CIN + lane * 4];
                dptr[0] = a0.x * r;
                dptr[1] = a0.y * r;
                dptr[2] = a0.z * r;
                dptr[3] = a0.w * r;
            }
            if (lane == 0) sflag[nloc] = (d > 0) ? 1.f : 0.f;
        }
    }
    __syncthreads();

    // Phase 2: SIMT matmul
    const int tx = tid % TX;
    const int ny = tid / TX;

    float acc[NT][4];
    float4 b0 = *reinterpret_cast<const float4*>(&C0[tx * 4]);
    float4 b1 = *reinterpret_cast<const float4*>(&C1[tx * 4]);
#pragma unroll
    for (int i = 0; i < NT; i++) {
        float s = sflag[ny * NT + i];
        acc[i][0] = b0.x + s * b1.x;
        acc[i][1] = b0.y + s * b1.y;
        acc[i][2] = b0.z + s * b1.z;
        acc[i][3] = b0.w + s * b1.w;
    }

#pragma unroll 8
    for (int k = 0; k < K; k++) {
        float4 w = *reinterpret_cast<const float4*>(&Ws[k * COUT + tx * 4]);
#pragma unroll
        for (int i = 0; i < NT; i++) {
            float v = Is[(ny * NT + i) * LDI + k];
            acc[i][0] += v * w.x;
            acc[i][1] += v * w.y;
            acc[i][2] += v * w.z;
            acc[i][3] += v * w.w;
        }
    }

#pragma unroll
    for (int i = 0; i < NT; i++) {
        int node = base + ny * NT + i;
        float4 o;
        o.x = fmaxf(acc[i][0], 0.f);
        o.y = fmaxf(acc[i][1], 0.f);
        o.z = fmaxf(acc[i][2], 0.f);
        o.w = fmaxf(acc[i][3], 0.f);
        *reinterpret_cast<float4*>(&out[(size_t)node * COUT + tx * 4]) = o;
    }
}

// ---------------------------------------------------------------------------
// Fused gather + TF32 wmma combine (big layers):
//   out = act([h | rdeg*sum_nbr h] @ Wt + b)
// 512 threads (16 warps), BN = 128 nodes/block.
// Gather unrolled 4x with independent accumulators (MLP=4 per slot chain).
// ---------------------------------------------------------------------------
template <int CIN, int COUT, int ACT>
__global__ void __launch_bounds__(512)
wmma_fused_kernel(const float* __restrict__ h,
                  const int* __restrict__ rowoff,
                  const int* __restrict__ deg,
                  const int* __restrict__ col,
                  const float* __restrict__ rdeg,
                  const float* __restrict__ Wt,
                  const float* __restrict__ bias,
                  float* __restrict__ out) {
    constexpr int K   = 2 * CIN;
    constexpr int BN  = 128;
    constexpr int LDI = K + 4;
    constexpr int JT  = COUT / 32;
    constexpr int C4  = CIN / 4;
    constexpr int SLOTS = 32 / C4;
    static_assert(COUT <= K, "staging reuse requires COUT <= K");

    extern __shared__ float sm[];
    float* Is = sm;                  // [BN][LDI]  inputs (tf32), later outputs
    float* Bs = Is + BN * LDI;       // [COUT]

    const int tid  = threadIdx.x;
    const int base = blockIdx.x * BN;

    if (tid < COUT) Bs[tid] = bias[tid];

    // ---- Phase 1a: stage self rows (tf32) ----
    for (int i = tid; i < BN * C4; i += 512) {
        int n = i / C4, q = i % C4;
        float4 v = reinterpret_cast<const float4*>(h)[(size_t)(base + n) * C4 + q];
        float* d = &Is[n * LDI + q * 4];
        d[0] = f2tf32(v.x); d[1] = f2tf32(v.y); d[2] = f2tf32(v.z); d[3] = f2tf32(v.w);
    }

    // ---- Phase 1b: in-block gather -> Is[n][CIN..K), 8 nodes per warp ----
    {
        const int warp = tid >> 5;
        const int lane = tid & 31;
        const int slot = lane / C4;
        const int c    = lane % C4;
        const float4* h4 = reinterpret_cast<const float4*>(h);

#pragma unroll
        for (int j = 0; j < BN / 16; j++) {
            int nloc = warp * (BN / 16) + j;
            int node = base + nloc;
            int st = rowoff[node];
            int d  = deg[node];
            float4 a0 = make_float4(0, 0, 0, 0), a1 = make_float4(0, 0, 0, 0);
            float4 a2 = make_float4(0, 0, 0, 0), a3 = make_float4(0, 0, 0, 0);
            int ni = slot;
            for (; ni + 3 * SLOTS < d; ni += 4 * SLOTS) {
                int i0 = col[st + ni];
                int i1 = col[st + ni + SLOTS];
                int i2 = col[st + ni + 2 * SLOTS];
                int i3 = col[st + ni + 3 * SLOTS];
                float4 v0 = h4[(size_t)i0 * C4 + c];
                float4 v1 = h4[(size_t)i1 * C4 + c];
                float4 v2 = h4[(size_t)i2 * C4 + c];
                float4 v3 = h4[(size_t)i3 * C4 + c];
                f4add(a0, v0); f4add(a1, v1); f4add(a2, v2); f4add(a3, v3);
            }
            for (; ni < d; ni += SLOTS) {
                int i0 = col[st + ni];
                f4add(a0, h4[(size_t)i0 * C4 + c]);
            }
            f4add(a0, a1); f4add(a2, a3); f4add(a0, a2);
#pragma unroll
            for (int off = 16; off >= C4; off >>= 1) {
                a0.x += __shfl_xor_sync(0xFFFFFFFFu, a0.x, off);
                a0.y += __shfl_xor_sync(0xFFFFFFFFu, a0.y, off);
                a0.z += __shfl_xor_sync(0xFFFFFFFFu, a0.z, off);
                a0.w += __shfl_xor_sync(0xFFFFFFFFu, a0.w, off);
            }
            if (lane < C4) {
                float r = rdeg[node];
                float* dptr = &Is[nloc * LDI + CIN + lane * 4];
                dptr[0] = f2tf32(a0.x * r);
                dptr[1] = f2tf32(a0.y * r);
                dptr[2] = f2tf32(a0.z * r);
                dptr[3] = f2tf32(a0.w * r);
            }
        }
    }
    __syncthreads();

    // ---- Phase 2: wmma ----
    const int warp = tid >> 5;
    const int nt   = warp & 7;       // node tile (16 rows)
    const int ch   = warp >> 3;      // col half

    wmma::fragment<wmma::accumulator, 16, 16, 8, float> fc[JT];
#pragma unroll
    for (int j = 0; j < JT; j++) wmma::fill_fragment(fc[j], 0.0f);

#pragma unroll
    for (int k8 = 0; k8 < K / 8; k8++) {
        wmma::fragment<wmma::matrix_a, 16, 16, 8, wmma::precision::tf32, wmma::row_major> fa;
        wmma::load_matrix_sync(fa, &Is[nt * 16 * LDI + k8 * 8], LDI);
#pragma unroll
        for (int j = 0; j < JT; j++) {
            wmma::fragment<wmma::matrix_b, 16, 16, 8, wmma::precision::tf32, wmma::row_major> fb;
            wmma::load_matrix_sync(fb, &Wt[k8 * 8 * COUT + (ch * JT + j) * 16], COUT);
            wmma::mma_sync(fc[j], fa, fb, fc[j]);
        }
    }
    __syncthreads();   // all warps done reading Is

    // Stash accumulators into Is (reused as [BN][LDI] output staging)
#pragma unroll
    for (int j = 0; j < JT; j++)
        wmma::store_matrix_sync(&Is[nt * 16 * LDI + (ch * JT + j) * 16],
                                fc[j], LDI, wmma::mem_row_major);
    __syncthreads();

    // Epilogue: bias + activation + coalesced store
    for (int i = tid; i < BN * COUT / 4; i += 512) {
        int n = i / (COUT / 4), q = i % (COUT / 4);
        float4 v = *reinterpret_cast<float4*>(&Is[n * LDI + q * 4]);
        float4 b4 = *reinterpret_cast<const float4*>(&Bs[q * 4]);
        float4 o;
        o.x = actf<ACT>(v.x + b4.x);
        o.y = actf<ACT>(v.y + b4.y);
        o.z = actf<ACT>(v.z + b4.z);
        o.w = actf<ACT>(v.w + b4.w);
        reinterpret_cast<float4*>(out)[(size_t)(base + n) * (COUT / 4) + q] = o;
    }
}

// ---------------------------------------------------------------------------
// Launch
// ---------------------------------------------------------------------------
static inline int wmma_smem_bytes(int K, int COUT) {
    return (128 * (K + 4) + COUT) * (int)sizeof(float);
}

extern "C" void kernel_launch(void* const* d_in, const int* in_sizes, int n_in,
                              void* d_out, int out_size) {
    const float* x     = (const float*)d_in[0];
    const int*   ei    = (const int*)d_in[1];      // [2, E]
    const float* W_lin = (const float*)d_in[3];
    const float* b_lin = (const float*)d_in[4];
    const float* Ws3   = (const float*)d_in[5];
    const float* Wn3   = (const float*)d_in[6];
    const float* b3    = (const float*)d_in[7];
    const float* Ws2   = (const float*)d_in[8];
    const float* Wn2   = (const float*)d_in[9];
    const float* b2    = (const float*)d_in[10];
    const float* Ws1   = (const float*)d_in[11];
    const float* Wn1   = (const float*)d_in[12];
    const float* b1    = (const float*)d_in[13];
    float* out = (float*)d_out;

    const int* src = ei;
    const int* dst = ei + NE;

    float *h1, *h2, *rdeg, *W1t, *W2t, *W3f, *c0, *c1;
    int *deg, *rowoff, *cursor, *col, *bsum;
    cudaGetSymbolAddress((void**)&h1,     g_h1);
    cudaGetSymbolAddress((void**)&h2,     g_h2);
    cudaGetSymbolAddress((void**)&rdeg,   g_rdeg);
    cudaGetSymbolAddress((void**)&W1t,    g_W1t);
    cudaGetSymbolAddress((void**)&W2t,    g_W2t);
    cudaGetSymbolAddress((void**)&W3f,    g_W3f);
    cudaGetSymbolAddress((void**)&c0,     g_c0);
    cudaGetSymbolAddress((void**)&c1,     g_c1);
    cudaGetSymbolAddress((void**)&deg,    g_deg);
    cudaGetSymbolAddress((void**)&rowoff, g_rowoff);
    cudaGetSymbolAddress((void**)&cursor, g_cursor);
    cudaGetSymbolAddress((void**)&col,    g_col);
    cudaGetSymbolAddress((void**)&bsum,   g_bsum);

    const int wsmem_L1 = wmma_smem_bytes(128, 128);   // ~66.5KB -> 2 CTA/SM
    const int wsmem_L2 = wmma_smem_bytes(64, 64);     // ~34.3KB -> 4 CTA/SM
    cudaFuncSetAttribute((const void*)wmma_fused_kernel<64, 128, 2>,
                         cudaFuncAttributeMaxDynamicSharedMemorySize, wsmem_L1 + 1024);
    cudaFuncSetAttribute((const void*)wmma_fused_kernel<32, 64, 1>,
                         cudaFuncAttributeMaxDynamicSharedMemorySize, wsmem_L2 + 1024);

    const int T  = 256;
    const int NB = NN / 64;          // block3 grid
    const int WB = NN / 128;         // wmma grid

    // ---- CSR build + weight prep/fold ----
    zero2_int<<<NN / T, T>>>(deg, cursor);
    deg_kernel<<<NE / T, T>>>(dst, deg);
    scanA<<<512, 256>>>(deg, rowoff, bsum, rdeg);
    scanB<<<1, 512>>>(bsum);
    scanC<<<512, 256>>>(rowoff, bsum);
    fill_kernel<<<NE / T, T>>>(src, dst, rowoff, cursor, col);
    prep_w<<<65, 256>>>(Ws1, Wn1, Ws2, Wn2, W_lin, b_lin, Ws3, Wn3, b3);

    // ---- Block3 (Linear folded): x -> h1 (16->32, relu) ----
    block3_fused_kernel<<<NB, T>>>(x, rowoff, deg, col, rdeg, W3f, c0, c1, h1);

    // ---- Block2: 32 -> 64, relu (fused gather + wmma tf32) ----
    wmma_fused_kernel<32, 64, 1><<<WB, 512, wsmem_L2>>>(
        h1, rowoff, deg, col, rdeg, W2t, b2, h2);

    // ---- Block1: 64 -> 128, sigmoid -> d_out (fused gather + wmma tf32) ----
    wmma_fused_kernel<64, 128, 2><<<WB, 512, wsmem_L1>>>(
        h2, rowoff, deg, col, rdeg, W1t, b1, out);
}